// round 1
// baseline (speedup 1.0000x reference)
#include <cuda_runtime.h>
#include <cstddef>

// Problem dims
// B=1024, F=512, N=8
// inputs: vx, ax, W1, b1, W2, b2, conv1_w, conv1_b, conv2_w, conv2_b

// ---------------- scratch (static device memory; no allocation) ----------------
__device__ float g_xcat[1024 * 1024];        // [B][2F]
__device__ float g_h[1024 * 8 * 512];        // [B][N][F]
__device__ float g_va[1024 * 512 * 8];       // [B][F][N]  (i-contiguous)
__device__ float g_p[1024 * 512 * 4];        // [B][F][4]  pooled
__device__ float g_wA[512 * 512 * 3];        // dj-summed conv1 weights [c][f][3]
__device__ float g_A2[512 * 2048];           // collapsed conv2+mean [c][f*4+q]

// ---------------- tiny preprocessing kernels ----------------
__global__ void concat_kernel(const float* __restrict__ vx, const float* __restrict__ ax) {
    int i = blockIdx.x * blockDim.x + threadIdx.x;   // 0 .. 1024*1024-1
    int b = i >> 10, k = i & 1023;
    g_xcat[i] = (k < 512) ? vx[b * 512 + k] : ax[b * 512 + (k - 512)];
}

__global__ void pre_wA_kernel(const float* __restrict__ w) {
    int i = blockIdx.x * blockDim.x + threadIdx.x;   // 0 .. 512*512*3-1  (c,f,di)
    g_wA[i] = w[i * 3 + 0] + w[i * 3 + 1] + w[i * 3 + 2];
}

__global__ void pre_A2_kernel(const float* __restrict__ w2) {
    int idx = blockIdx.x * blockDim.x + threadIdx.x; // 0 .. 512*512*4-1
    int q = idx & 3;
    int cf = idx >> 2;
    int f = cf & 511;
    int c = cf >> 9;
    int ip = q >> 1, jp = q & 1;
    const float* wb = w2 + (size_t)(c * 512 + f) * 9;
    float s = 0.f;
    #pragma unroll
    for (int i = 0; i < 2; i++)
        #pragma unroll
        for (int j = 0; j < 2; j++)
            s += wb[(ip - i + 1) * 3 + (jp - j + 1)];
    g_A2[(size_t)c * 2048 + f * 4 + q] = 0.25f * s;
}

// ---------------- tiled GEMM:  C = epi( A * B^T + bias ) ----------------
// A: [M][K] row-major (lda), B: [N][K] row-major (ldb), both K-contiguous.
// 128x128 tile, BK=16, 256 threads, 8x8 microtile.
// VA_EPI=false: C[m*ldc+n] = relu(acc + bias[n])
// VA_EPI=true : va[(m*512+n)*8 + z] = vx[m*512+n] * relu(acc + bias[n])
template <bool VA_EPI>
__global__ void __launch_bounds__(256) gemm_kernel(
    const float* __restrict__ A, const float* __restrict__ Bm,
    const float* __restrict__ bias, float* __restrict__ C,
    int K, int lda, int ldb, int ldc,
    const float* __restrict__ vx,
    int strideA, int strideB, int strideBias)
{
    __shared__ float sA[16 * 132];
    __shared__ float sB[16 * 132];

    const int tid = threadIdx.x;
    const int tx = tid & 15;        // n-dir
    const int ty = tid >> 4;        // m-dir
    const int m0 = blockIdx.y * 128;
    const int n0 = blockIdx.x * 128;
    const int z  = blockIdx.z;

    A    += (size_t)z * strideA;
    Bm   += (size_t)z * strideB;
    bias += (size_t)z * strideBias;

    float acc[8][8];
    #pragma unroll
    for (int i = 0; i < 8; i++)
        #pragma unroll
        for (int j = 0; j < 8; j++) acc[i][j] = 0.f;

    // staging slots: 512 float4 per tile, 2 per thread
    const int sa = tid, sb = tid + 256;
    const int mA0 = sa >> 2, kq0 = (sa & 3) << 2;
    const int mA1 = sb >> 2, kq1 = (sb & 3) << 2;

    for (int k0 = 0; k0 < K; k0 += 16) {
        float4 a0 = *(const float4*)(A  + (size_t)(m0 + mA0) * lda + k0 + kq0);
        float4 a1 = *(const float4*)(A  + (size_t)(m0 + mA1) * lda + k0 + kq1);
        float4 b0 = *(const float4*)(Bm + (size_t)(n0 + mA0) * ldb + k0 + kq0);
        float4 b1 = *(const float4*)(Bm + (size_t)(n0 + mA1) * ldb + k0 + kq1);
        __syncthreads();
        sA[(kq0 + 0) * 132 + mA0] = a0.x; sA[(kq0 + 1) * 132 + mA0] = a0.y;
        sA[(kq0 + 2) * 132 + mA0] = a0.z; sA[(kq0 + 3) * 132 + mA0] = a0.w;
        sA[(kq1 + 0) * 132 + mA1] = a1.x; sA[(kq1 + 1) * 132 + mA1] = a1.y;
        sA[(kq1 + 2) * 132 + mA1] = a1.z; sA[(kq1 + 3) * 132 + mA1] = a1.w;
        sB[(kq0 + 0) * 132 + mA0] = b0.x; sB[(kq0 + 1) * 132 + mA0] = b0.y;
        sB[(kq0 + 2) * 132 + mA0] = b0.z; sB[(kq0 + 3) * 132 + mA0] = b0.w;
        sB[(kq1 + 0) * 132 + mA1] = b1.x; sB[(kq1 + 1) * 132 + mA1] = b1.y;
        sB[(kq1 + 2) * 132 + mA1] = b1.z; sB[(kq1 + 3) * 132 + mA1] = b1.w;
        __syncthreads();

        #pragma unroll
        for (int k = 0; k < 16; k++) {
            float4 av0 = *(const float4*)&sA[k * 132 + ty * 8];
            float4 av1 = *(const float4*)&sA[k * 132 + ty * 8 + 4];
            float4 bv0 = *(const float4*)&sB[k * 132 + tx * 8];
            float4 bv1 = *(const float4*)&sB[k * 132 + tx * 8 + 4];
            float av[8] = {av0.x, av0.y, av0.z, av0.w, av1.x, av1.y, av1.z, av1.w};
            float bv[8] = {bv0.x, bv0.y, bv0.z, bv0.w, bv1.x, bv1.y, bv1.z, bv1.w};
            #pragma unroll
            for (int i = 0; i < 8; i++)
                #pragma unroll
                for (int j = 0; j < 8; j++)
                    acc[i][j] += av[i] * bv[j];
        }
    }

    if (!VA_EPI) {
        #pragma unroll
        for (int i = 0; i < 8; i++) {
            int m = m0 + ty * 8 + i;
            #pragma unroll
            for (int j = 0; j < 8; j++) {
                int n = n0 + tx * 8 + j;
                C[(size_t)m * ldc + n] = fmaxf(acc[i][j] + bias[n], 0.f);
            }
        }
    } else {
        #pragma unroll
        for (int i = 0; i < 8; i++) {
            int b = m0 + ty * 8 + i;
            #pragma unroll
            for (int j = 0; j < 8; j++) {
                int g = n0 + tx * 8 + j;
                float att = fmaxf(acc[i][j] + bias[g], 0.f);
                C[((size_t)b * 512 + g) * 8 + z] = vx[(size_t)b * 512 + g] * att;
            }
        }
    }
}

// ---------------- reduced conv1 + maxpool ----------------
// For each (b,c): three 3-tap 1-D convs along i (M, and dj=0 / dj=2 correction
// slices), then fused 4x4 maxpool using yL = yM - convB, yR = yM - convC.
// Block: 512 threads = 16 b (warp index) x 32 c (lane). Tile F in chunks of 16.
#define CT 32
#define BT 16
#define FK 16
__global__ void __launch_bounds__(512) conv_pool_kernel(
    const float* __restrict__ c1w, const float* __restrict__ c1b)
{
    __shared__ float s_va[BT * FK * 8];   // [bb][f][i]  2048 floats
    __shared__ float s_w[FK * CT * 9];    // [f][c][9]   4608 floats

    const int tid = threadIdx.x;
    const int cb = tid & 31;              // lane -> c
    const int bb = tid >> 5;              // warp -> b
    const int c0 = blockIdx.x * CT;
    const int b0 = blockIdx.y * BT;

    float accA[8], accB[8], accC[8];
    #pragma unroll
    for (int i = 0; i < 8; i++) { accA[i] = 0.f; accB[i] = 0.f; accC[i] = 0.f; }

    for (int f0 = 0; f0 < 512; f0 += FK) {
        __syncthreads();
        {   // va tile: 512 float4 slots, 1 per thread; smem layout == gmem layout
            int s = tid;
            int b_l = s >> 5;             // 32 float4 per b-row (FK*8/4)
            int r = s & 31;
            const float4* src = (const float4*)(g_va + ((size_t)(b0 + b_l) * 512 + f0) * 8);
            ((float4*)s_va)[s] = src[r];
        }
        // weights: [f][c][9]; 9 floats per thread
        for (int idx = tid; idx < FK * CT * 9; idx += 512) {
            int k = idx % 9;
            int fc = idx / 9;
            int c_l = fc & 31;
            int f_l = fc >> 5;
            int c = c0 + c_l, f = f0 + f_l;
            float w;
            if (k < 3)       w = g_wA[((size_t)c * 512 + f) * 3 + k];
            else if (k < 6)  w = c1w[(((size_t)c * 512 + f) * 3 + (k - 3)) * 3 + 0];
            else             w = c1w[(((size_t)c * 512 + f) * 3 + (k - 6)) * 3 + 2];
            s_w[idx] = w;
        }
        __syncthreads();

        #pragma unroll 4
        for (int f = 0; f < FK; f++) {
            float v[10];
            float4 p0 = *(const float4*)&s_va[(bb * FK + f) * 8];       // broadcast in warp
            float4 p1 = *(const float4*)&s_va[(bb * FK + f) * 8 + 4];
            v[0] = 0.f;
            v[1] = p0.x; v[2] = p0.y; v[3] = p0.z; v[4] = p0.w;
            v[5] = p1.x; v[6] = p1.y; v[7] = p1.z; v[8] = p1.w;
            v[9] = 0.f;
            const float* w = &s_w[(f * 32 + cb) * 9];                    // stride 9: conflict-free
            float wa0 = w[0], wa1 = w[1], wa2 = w[2];
            float wb0 = w[3], wb1 = w[4], wb2 = w[5];
            float wc0 = w[6], wc1 = w[7], wc2 = w[8];
            #pragma unroll
            for (int i = 0; i < 8; i++) {
                accA[i] += wa0 * v[i] + wa1 * v[i + 1] + wa2 * v[i + 2];
                accB[i] += wb0 * v[i] + wb1 * v[i + 1] + wb2 * v[i + 2];
                accC[i] += wc0 * v[i] + wc1 * v[i + 1] + wc2 * v[i + 2];
            }
        }
    }

    // epilogue: pooled [2x2] per (b,c)
    int c = c0 + cb, b = b0 + bb;
    float bias = c1b[c];
    float m00 = -1e30f, m01 = -1e30f, m10 = -1e30f, m11 = -1e30f;
    #pragma unroll
    for (int i = 0; i < 8; i++) {
        float yM = accA[i];
        float yL = yM - accB[i];   // j=0 column: missing kj=0 tap
        float yR = yM - accC[i];   // j=7 column: missing kj=2 tap
        float vL = fmaxf(yL, yM);
        float vR = fmaxf(yR, yM);
        if (i < 4) { m00 = fmaxf(m00, vL); m01 = fmaxf(m01, vR); }
        else       { m10 = fmaxf(m10, vL); m11 = fmaxf(m11, vR); }
    }
    float* p = &g_p[((size_t)b * 512 + c) * 4];
    p[0] = m00 + bias; p[1] = m01 + bias; p[2] = m10 + bias; p[3] = m11 + bias;
}

// ---------------- launch ----------------
extern "C" void kernel_launch(void* const* d_in, const int* in_sizes, int n_in,
                              void* d_out, int out_size) {
    (void)in_sizes; (void)n_in; (void)out_size;
    const float* vx  = (const float*)d_in[0];
    const float* ax  = (const float*)d_in[1];
    const float* W1  = (const float*)d_in[2];
    const float* b1  = (const float*)d_in[3];
    const float* W2  = (const float*)d_in[4];
    const float* b2  = (const float*)d_in[5];
    const float* c1w = (const float*)d_in[6];
    const float* c1b = (const float*)d_in[7];
    const float* c2w = (const float*)d_in[8];
    const float* c2b = (const float*)d_in[9];
    float* out = (float*)d_out;

    void *p_xcat, *p_h, *p_va, *p_p, *p_A2;
    cudaGetSymbolAddress(&p_xcat, g_xcat);
    cudaGetSymbolAddress(&p_h,    g_h);
    cudaGetSymbolAddress(&p_va,   g_va);
    cudaGetSymbolAddress(&p_p,    g_p);
    cudaGetSymbolAddress(&p_A2,   g_A2);

    // preprocessing
    concat_kernel<<<2048, 512>>>(vx, ax);
    pre_wA_kernel<<<3072, 256>>>(c1w);
    pre_A2_kernel<<<4096, 256>>>(c2w);

    // GEMM1: h[1024][4096] = relu(xcat[1024][1024] * W1^T + b1)
    gemm_kernel<false><<<dim3(32, 8, 1), 256>>>(
        (const float*)p_xcat, W1, b1, (float*)p_h,
        1024, 1024, 1024, 4096, nullptr, 0, 0, 0);

    // GEMM2 (batched over n): va[b][g][n] = vx[b][g] * relu(h_n * W2_n^T + b2_n)
    gemm_kernel<true><<<dim3(4, 8, 8), 256>>>(
        (const float*)p_h, W2, b2, (float*)p_va,
        512, 4096, 512, 0, vx, 512, 512 * 512, 512);

    // reduced conv1 + maxpool -> g_p
    conv_pool_kernel<<<dim3(16, 64), 512>>>(c1w, c1b);

    // GEMM3: out[1024][512] = relu(p[1024][2048] * A2^T + conv2_b)
    gemm_kernel<false><<<dim3(4, 8, 1), 256>>>(
        (const float*)p_p, (const float*)p_A2, c2b, out,
        2048, 2048, 2048, 512, nullptr, 0, 0, 0);
}

// round 3
// speedup vs baseline: 1.7155x; 1.7155x over previous
#include <cuda_runtime.h>
#include <cuda_bf16.h>
#include <cstdint>
#include <cstddef>

// B=1024, F=512, N=8
// concat -> GEMM1 (SIMT) -> GEMM2 (SIMT, writes vaT) -> build X3/W3 (bf16 3-split)
// -> HMMA conv GEMM (M=8192, N=1536, K=4608 bf16) -> pool -> GEMM3 (SIMT)

// ---------------- static scratch ----------------
__device__ float g_xcat[1024 * 1024];                  // [B][2F]
__device__ float g_h[1024 * 8 * 512];                  // [B][N][F]
__device__ float g_vaT[1024 * 8 * 512];                // [B][i][F]
__device__ float g_p[1024 * 512 * 4];                  // [B][F][4]
__device__ float g_A2[512 * 2048];                     // collapsed conv2+mean
__device__ unsigned short g_X3[(size_t)8192 * 4608];   // bf16 [r=(b,i)][K3]
__device__ unsigned short g_W3[(size_t)1536 * 4608];   // bf16 [n=t*512+c][K3]
__device__ float g_Y[(size_t)8192 * 1536];             // conv GEMM output

// ---------------- tiny preprocessing kernels ----------------
__global__ void concat_kernel(const float* __restrict__ vx, const float* __restrict__ ax) {
    int i = blockIdx.x * blockDim.x + threadIdx.x;
    int b = i >> 10, k = i & 1023;
    g_xcat[i] = (k < 512) ? vx[b * 512 + k] : ax[b * 512 + (k - 512)];
}

__global__ void pre_A2_kernel(const float* __restrict__ w2) {
    int idx = blockIdx.x * blockDim.x + threadIdx.x;  // 512*512*4
    int q = idx & 3;
    int cf = idx >> 2;
    int f = cf & 511;
    int c = cf >> 9;
    int ip = q >> 1, jp = q & 1;
    const float* wb = w2 + (size_t)(c * 512 + f) * 9;
    float s = 0.f;
    #pragma unroll
    for (int i = 0; i < 2; i++)
        #pragma unroll
        for (int j = 0; j < 2; j++)
            s += wb[(ip - i + 1) * 3 + (jp - j + 1)];
    g_A2[(size_t)c * 2048 + f * 4 + q] = 0.25f * s;
}

// ---------------- bf16 split helpers ----------------
union Pack8 { unsigned short s[8]; uint4 v; };
__device__ __forceinline__ void split_hi_lo(float x, unsigned short& hi, unsigned short& lo) {
    __nv_bfloat16 h = __float2bfloat16(x);
    float hf = __bfloat162float(h);
    __nv_bfloat16 l = __float2bfloat16(x - hf);
    hi = __bfloat16_as_ushort(h);
    lo = __bfloat16_as_ushort(l);
}

// X3[r=(b,i)][blk*1536 + di*512 + f], blocks = [hi, lo, hi]
__global__ void build_x3_kernel() {
    int idx = blockIdx.x * blockDim.x + threadIdx.x;   // 8192*3*64
    int fg = idx & 63;
    int di = (idx >> 6) % 3;
    int r  = idx / 192;
    int b = r >> 3, i = r & 7;
    int src = i + di - 1;
    float vals[8];
    if (src >= 0 && src < 8) {
        const float4* p = (const float4*)(g_vaT + ((size_t)(b * 8 + src) * 512) + fg * 8);
        float4 x0 = p[0], x1 = p[1];
        vals[0] = x0.x; vals[1] = x0.y; vals[2] = x0.z; vals[3] = x0.w;
        vals[4] = x1.x; vals[5] = x1.y; vals[6] = x1.z; vals[7] = x1.w;
    } else {
        #pragma unroll
        for (int j = 0; j < 8; j++) vals[j] = 0.f;
    }
    Pack8 hi, lo;
    #pragma unroll
    for (int j = 0; j < 8; j++) split_hi_lo(vals[j], hi.s[j], lo.s[j]);
    size_t e0 = (size_t)r * 4608 + di * 512 + fg * 8;
    *(uint4*)(g_X3 + e0)        = hi.v;   // blk0 (pairs Wh)
    *(uint4*)(g_X3 + e0 + 1536) = lo.v;   // blk1 (pairs Wh)
    *(uint4*)(g_X3 + e0 + 3072) = hi.v;   // blk2 (pairs Wl)
}

// W3[n=t*512+c][blk*1536 + di*512 + f], blocks = [hi, hi, lo]
__global__ void build_w3_kernel(const float* __restrict__ c1w) {
    int idx = blockIdx.x * blockDim.x + threadIdx.x;   // 1536*3*64
    int fg = idx & 63;
    int di = (idx >> 6) % 3;
    int n  = idx / 192;
    int t = n >> 9, c = n & 511;
    Pack8 hi, lo;
    #pragma unroll
    for (int j = 0; j < 8; j++) {
        int f = fg * 8 + j;
        size_t base = ((size_t)(c * 512 + f) * 3 + di) * 3;
        float w;
        if (t == 0)      w = c1w[base] + c1w[base + 1] + c1w[base + 2];
        else if (t == 1) w = c1w[base];
        else             w = c1w[base + 2];
        split_hi_lo(w, hi.s[j], lo.s[j]);
    }
    size_t e0 = (size_t)n * 4608 + di * 512 + fg * 8;
    *(uint4*)(g_W3 + e0)        = hi.v;
    *(uint4*)(g_W3 + e0 + 1536) = hi.v;
    *(uint4*)(g_W3 + e0 + 3072) = lo.v;
}

// ---------------- HMMA conv GEMM: Y[8192][1536] = X3 * W3^T ----------------
// 128x128 CTA tile, BK=32, 8 warps (warp tile 64x32), mma.m16n8k16 bf16.
__device__ __forceinline__ uint32_t smem_u32(const void* p) {
    uint32_t a;
    asm("{ .reg .u64 t; cvta.to.shared.u64 t, %1; cvt.u32.u64 %0, t; }" : "=r"(a) : "l"(p));
    return a;
}
__device__ __forceinline__ void ldmatrix_x4(uint32_t& r0, uint32_t& r1, uint32_t& r2, uint32_t& r3,
                                            uint32_t addr) {
    asm volatile("ldmatrix.sync.aligned.m8n8.x4.shared.b16 {%0,%1,%2,%3}, [%4];"
                 : "=r"(r0), "=r"(r1), "=r"(r2), "=r"(r3) : "r"(addr));
}
__device__ __forceinline__ void mma_16816(float* c, const uint32_t* a, const uint32_t* b) {
    asm volatile("mma.sync.aligned.m16n8k16.row.col.f32.bf16.bf16.f32 "
                 "{%0,%1,%2,%3}, {%4,%5,%6,%7}, {%8,%9}, {%0,%1,%2,%3};"
                 : "+f"(c[0]), "+f"(c[1]), "+f"(c[2]), "+f"(c[3])
                 : "r"(a[0]), "r"(a[1]), "r"(a[2]), "r"(a[3]), "r"(b[0]), "r"(b[1]));
}

#define LDK 40   // smem row stride in halves (80B: 16B-aligned, conflict-free ldmatrix)

__global__ void __launch_bounds__(256, 2) conv_hmma_kernel(
    const unsigned short* __restrict__ X, const unsigned short* __restrict__ Wm,
    float* __restrict__ Y)
{
    __shared__ __align__(16) unsigned short sA[2][128 * LDK];
    __shared__ __align__(16) unsigned short sB[2][128 * LDK];

    const int tid = threadIdx.x;
    const int wid = tid >> 5, lane = tid & 31;
    const int m0 = blockIdx.y * 128;
    const int n0 = blockIdx.x * 128;
    const int wm = (wid & 1) * 64;    // warp m offset
    const int wn = (wid >> 1) * 32;   // warp n offset

    // staging: each thread handles one row (tid>>1) and 2 of its 4 uint4 chunks
    const int sr = tid >> 1;
    const int sq = (tid & 1) * 2;

    const unsigned short* gA = X  + (size_t)(m0 + sr) * 4608 + sq * 8;
    const unsigned short* gB = Wm + (size_t)(n0 + sr) * 4608 + sq * 8;
    unsigned short* sAr = &sA[0][0] + sr * LDK + sq * 8;
    unsigned short* sBr = &sB[0][0] + sr * LDK + sq * 8;
    const int bufstep = 128 * LDK;

    float acc[4][4][4];
    #pragma unroll
    for (int i = 0; i < 4; i++)
        #pragma unroll
        for (int j = 0; j < 4; j++)
            #pragma unroll
            for (int q = 0; q < 4; q++) acc[i][j][q] = 0.f;

    // ldmatrix lane addressing (element offsets within a buffer)
    const uint32_t sA_base = smem_u32(&sA[0][0]);
    const uint32_t sB_base = smem_u32(&sB[0][0]);
    const int aRow = wm + (lane & 15);
    const int aKof = (lane >> 4) * 8;
    const int bRow = wn + ((lane & 7) | ((lane >> 4) << 3));
    const int bKof = ((lane >> 3) & 1) * 8;

    // preload chunk 0
    uint4 ra0 = *(const uint4*)(gA);
    uint4 ra1 = *(const uint4*)(gA + 8);
    uint4 rb0 = *(const uint4*)(gB);
    uint4 rb1 = *(const uint4*)(gB + 8);
    *(uint4*)(sAr)     = ra0;  *(uint4*)(sAr + 8) = ra1;
    *(uint4*)(sBr)     = rb0;  *(uint4*)(sBr + 8) = rb1;
    __syncthreads();

    const int NIT = 4608 / 32;   // 144
    for (int it = 0; it < NIT; it++) {
        const int cur = it & 1;
        const bool more = (it + 1) < NIT;
        if (more) {
            const unsigned short* pA = gA + (it + 1) * 32;
            const unsigned short* pB = gB + (it + 1) * 32;
            ra0 = *(const uint4*)(pA);
            ra1 = *(const uint4*)(pA + 8);
            rb0 = *(const uint4*)(pB);
            rb1 = *(const uint4*)(pB + 8);
        }

        const uint32_t aBuf = sA_base + cur * (bufstep * 2);
        const uint32_t bBuf = sB_base + cur * (bufstep * 2);
        #pragma unroll
        for (int ks = 0; ks < 32; ks += 16) {
            uint32_t af[4][4], bf[4][2];
            #pragma unroll
            for (int mt = 0; mt < 4; mt++)
                ldmatrix_x4(af[mt][0], af[mt][1], af[mt][2], af[mt][3],
                            aBuf + (uint32_t)(((aRow + mt * 16) * LDK + ks + aKof) * 2));
            #pragma unroll
            for (int np = 0; np < 2; np++)
                ldmatrix_x4(bf[np * 2][0], bf[np * 2][1], bf[np * 2 + 1][0], bf[np * 2 + 1][1],
                            bBuf + (uint32_t)(((bRow + np * 16) * LDK + ks + bKof) * 2));
            #pragma unroll
            for (int mt = 0; mt < 4; mt++)
                #pragma unroll
                for (int nt = 0; nt < 4; nt++)
                    mma_16816(acc[mt][nt], af[mt], bf[nt]);
        }

        if (more) {
            unsigned short* dA = sAr + (cur ^ 1) * bufstep;
            unsigned short* dB = sBr + (cur ^ 1) * bufstep;
            *(uint4*)(dA)     = ra0;  *(uint4*)(dA + 8) = ra1;
            *(uint4*)(dB)     = rb0;  *(uint4*)(dB + 8) = rb1;
        }
        __syncthreads();
    }

    // epilogue: c0,c1 -> (row, col..col+1); c2,c3 -> (row+8, ...)
    const int erow = lane >> 2;
    const int ecol = (lane & 3) * 2;
    #pragma unroll
    for (int mt = 0; mt < 4; mt++) {
        #pragma unroll
        for (int nt = 0; nt < 4; nt++) {
            int r = m0 + wm + mt * 16 + erow;
            int cidx = n0 + wn + nt * 8 + ecol;
            *(float2*)&Y[(size_t)r * 1536 + cidx] =
                make_float2(acc[mt][nt][0], acc[mt][nt][1]);
            *(float2*)&Y[(size_t)(r + 8) * 1536 + cidx] =
                make_float2(acc[mt][nt][2], acc[mt][nt][3]);
        }
    }
}

// ---------------- pool: Y -> g_p ----------------
__global__ void pool_kernel(const float* __restrict__ Y, const float* __restrict__ c1b) {
    int idx = blockIdx.x * blockDim.x + threadIdx.x;   // 1024*512
    int c = idx & 511, b = idx >> 9;
    float bias = c1b[c];
    float m00 = -1e30f, m01 = -1e30f, m10 = -1e30f, m11 = -1e30f;
    #pragma unroll
    for (int i = 0; i < 8; i++) {
        size_t base = (size_t)(b * 8 + i) * 1536;
        float yM = Y[base + c];
        float yB = Y[base + 512 + c];
        float yC = Y[base + 1024 + c];
        float vL = fmaxf(yM - yB, yM);
        float vR = fmaxf(yM - yC, yM);
        if (i < 4) { m00 = fmaxf(m00, vL); m01 = fmaxf(m01, vR); }
        else       { m10 = fmaxf(m10, vL); m11 = fmaxf(m11, vR); }
    }
    float4 out = make_float4(m00 + bias, m01 + bias, m10 + bias, m11 + bias);
    *(float4*)(g_p + (size_t)idx * 4) = out;
}

// ---------------- SIMT tiled GEMM ----------------
template <bool VA_EPI>
__global__ void __launch_bounds__(256) gemm_kernel(
    const float* __restrict__ A, const float* __restrict__ Bm,
    const float* __restrict__ bias, float* __restrict__ C,
    int K, int lda, int ldb, int ldc,
    const float* __restrict__ vx,
    int strideA, int strideB, int strideBias)
{
    __shared__ float sA[16 * 132];
    __shared__ float sB[16 * 132];

    const int tid = threadIdx.x;
    const int tx = tid & 15;
    const int ty = tid >> 4;
    const int m0 = blockIdx.y * 128;
    const int n0 = blockIdx.x * 128;
    const int z  = blockIdx.z;

    A    += (size_t)z * strideA;
    Bm   += (size_t)z * strideB;
    bias += (size_t)z * strideBias;

    float acc[8][8];
    #pragma unroll
    for (int i = 0; i < 8; i++)
        #pragma unroll
        for (int j = 0; j < 8; j++) acc[i][j] = 0.f;

    const int sa = tid, sb = tid + 256;
    const int mA0 = sa >> 2, kq0 = (sa & 3) << 2;
    const int mA1 = sb >> 2, kq1 = (sb & 3) << 2;

    for (int k0 = 0; k0 < K; k0 += 16) {
        float4 a0 = *(const float4*)(A  + (size_t)(m0 + mA0) * lda + k0 + kq0);
        float4 a1 = *(const float4*)(A  + (size_t)(m0 + mA1) * lda + k0 + kq1);
        float4 b0 = *(const float4*)(Bm + (size_t)(n0 + mA0) * ldb + k0 + kq0);
        float4 b1 = *(const float4*)(Bm + (size_t)(n0 + mA1) * ldb + k0 + kq1);
        __syncthreads();
        sA[(kq0 + 0) * 132 + mA0] = a0.x; sA[(kq0 + 1) * 132 + mA0] = a0.y;
        sA[(kq0 + 2) * 132 + mA0] = a0.z; sA[(kq0 + 3) * 132 + mA0] = a0.w;
        sA[(kq1 + 0) * 132 + mA1] = a1.x; sA[(kq1 + 1) * 132 + mA1] = a1.y;
        sA[(kq1 + 2) * 132 + mA1] = a1.z; sA[(kq1 + 3) * 132 + mA1] = a1.w;
        sB[(kq0 + 0) * 132 + mA0] = b0.x; sB[(kq0 + 1) * 132 + mA0] = b0.y;
        sB[(kq0 + 2) * 132 + mA0] = b0.z; sB[(kq0 + 3) * 132 + mA0] = b0.w;
        sB[(kq1 + 0) * 132 + mA1] = b1.x; sB[(kq1 + 1) * 132 + mA1] = b1.y;
        sB[(kq1 + 2) * 132 + mA1] = b1.z; sB[(kq1 + 3) * 132 + mA1] = b1.w;
        __syncthreads();

        #pragma unroll
        for (int k = 0; k < 16; k++) {
            float4 av0 = *(const float4*)&sA[k * 132 + ty * 8];
            float4 av1 = *(const float4*)&sA[k * 132 + ty * 8 + 4];
            float4 bv0 = *(const float4*)&sB[k * 132 + tx * 8];
            float4 bv1 = *(const float4*)&sB[k * 132 + tx * 8 + 4];
            float av[8] = {av0.x, av0.y, av0.z, av0.w, av1.x, av1.y, av1.z, av1.w};
            float bv[8] = {bv0.x, bv0.y, bv0.z, bv0.w, bv1.x, bv1.y, bv1.z, bv1.w};
            #pragma unroll
            for (int i = 0; i < 8; i++)
                #pragma unroll
                for (int j = 0; j < 8; j++)
                    acc[i][j] += av[i] * bv[j];
        }
    }

    if (!VA_EPI) {
        #pragma unroll
        for (int i = 0; i < 8; i++) {
            int m = m0 + ty * 8 + i;
            #pragma unroll
            for (int j = 0; j < 8; j++) {
                int n = n0 + tx * 8 + j;
                C[(size_t)m * ldc + n] = fmaxf(acc[i][j] + bias[n], 0.f);
            }
        }
    } else {
        #pragma unroll
        for (int i = 0; i < 8; i++) {
            int b = m0 + ty * 8 + i;
            #pragma unroll
            for (int j = 0; j < 8; j++) {
                int g = n0 + tx * 8 + j;
                float att = fmaxf(acc[i][j] + bias[g], 0.f);
                C[((size_t)b * 8 + z) * 512 + g] = vx[(size_t)b * 512 + g] * att;
            }
        }
    }
}

// ---------------- launch ----------------
extern "C" void kernel_launch(void* const* d_in, const int* in_sizes, int n_in,
                              void* d_out, int out_size) {
    (void)in_sizes; (void)n_in; (void)out_size;
    const float* vx  = (const float*)d_in[0];
    const float* ax  = (const float*)d_in[1];
    const float* W1  = (const float*)d_in[2];
    const float* b1  = (const float*)d_in[3];
    const float* W2  = (const float*)d_in[4];
    const float* b2  = (const float*)d_in[5];
    const float* c1w = (const float*)d_in[6];
    const float* c1b = (const float*)d_in[7];
    const float* c2w = (const float*)d_in[8];
    const float* c2b = (const float*)d_in[9];
    float* out = (float*)d_out;

    void *p_xcat, *p_h, *p_vaT, *p_p, *p_A2, *p_X3, *p_W3, *p_Y;
    cudaGetSymbolAddress(&p_xcat, g_xcat);
    cudaGetSymbolAddress(&p_h,    g_h);
    cudaGetSymbolAddress(&p_vaT,  g_vaT);
    cudaGetSymbolAddress(&p_p,    g_p);
    cudaGetSymbolAddress(&p_A2,   g_A2);
    cudaGetSymbolAddress(&p_X3,   g_X3);
    cudaGetSymbolAddress(&p_W3,   g_W3);
    cudaGetSymbolAddress(&p_Y,    g_Y);

    // preprocessing
    concat_kernel<<<2048, 512>>>(vx, ax);
    pre_A2_kernel<<<4096, 256>>>(c2w);
    build_w3_kernel<<<1152, 256>>>(c1w);

    // GEMM1: h = relu(xcat * W1^T + b1)
    gemm_kernel<false><<<dim3(32, 8, 1), 256>>>(
        (const float*)p_xcat, W1, b1, (float*)p_h,
        1024, 1024, 1024, 4096, nullptr, 0, 0, 0);

    // GEMM2 (batched over unit z): vaT[b][z][g] = vx * relu(h_z * W2_z^T + b2_z)
    gemm_kernel<true><<<dim3(4, 8, 8), 256>>>(
        (const float*)p_h, W2, b2, (float*)p_vaT,
        512, 4096, 512, 0, vx, 512, 512 * 512, 512);

    // build bf16-split shifted operand, then HMMA conv GEMM
    build_x3_kernel<<<6144, 256>>>();
    conv_hmma_kernel<<<dim3(12, 64), 256>>>(
        (const unsigned short*)p_X3, (const unsigned short*)p_W3, (float*)p_Y);

    // pool -> g_p
    pool_kernel<<<2048, 256>>>((const float*)p_Y, c1b);

    // GEMM3: out = relu(p * A2^T + c2b)
    gemm_kernel<false><<<dim3(4, 8, 1), 256>>>(
        (const float*)p_p, (const float*)p_A2, c2b, out,
        2048, 2048, 2048, 512, nullptr, 0, 0, 0);
}

// round 4
// speedup vs baseline: 2.7952x; 1.6294x over previous
#include <cuda_runtime.h>
#include <cuda_bf16.h>
#include <cstdint>
#include <cstddef>

// B=1024, F=512, N=8
// All heavy math on HMMA bf16 with 3-term split (A=[hi|lo|hi], B=[hi|hi|lo], err ~4e-6/stage).
// concat+split -> HMMA G1 (writes h split) -> HMMA G2 (writes vaT) -> build X3
// -> HMMA conv (256x128 tile) -> pool (writes p split) -> HMMA G3 -> out

#define LDK 40   // smem row stride in halves (80B, conflict-free ldmatrix)

// ---------------- static scratch ----------------
__device__ unsigned short g_xcat3[(size_t)1024 * 3072];   // A-mode split of [vx|ax]
__device__ unsigned short g_W13[(size_t)4096 * 3072];     // B-mode split of W1
__device__ unsigned short g_h3[(size_t)8 * 1024 * 1536];  // [z][b][3*512] A-mode
__device__ unsigned short g_W23[(size_t)4096 * 1536];     // B-mode split of W2
__device__ float g_vaT[1024 * 8 * 512];                   // [B][i][F]
__device__ unsigned short g_X3[(size_t)8192 * 4608];      // conv A (A-mode, di-shifted)
__device__ unsigned short g_W3[(size_t)1536 * 4608];      // conv B (B-mode)
__device__ float g_Y[(size_t)8192 * 1536];                // conv out
__device__ unsigned short g_p3[(size_t)1024 * 6144];      // pooled, A-mode split
__device__ unsigned short g_A23[(size_t)512 * 6144];      // conv2-collapsed, B-mode split

// ---------------- helpers ----------------
union Pack8 { unsigned short s[8]; uint4 v; };
__device__ __forceinline__ void split_hi_lo(float x, unsigned short& hi, unsigned short& lo) {
    __nv_bfloat16 h = __float2bfloat16(x);
    float hf = __bfloat162float(h);
    __nv_bfloat16 l = __float2bfloat16(x - hf);
    hi = __bfloat16_as_ushort(h);
    lo = __bfloat16_as_ushort(l);
}
__device__ __forceinline__ uint32_t smem_u32(const void* p) {
    uint32_t a;
    asm("{ .reg .u64 t; cvta.to.shared.u64 t, %1; cvt.u32.u64 %0, t; }" : "=r"(a) : "l"(p));
    return a;
}
__device__ __forceinline__ void ldmatrix_x4(uint32_t& r0, uint32_t& r1, uint32_t& r2, uint32_t& r3,
                                            uint32_t addr) {
    asm volatile("ldmatrix.sync.aligned.m8n8.x4.shared.b16 {%0,%1,%2,%3}, [%4];"
                 : "=r"(r0), "=r"(r1), "=r"(r2), "=r"(r3) : "r"(addr));
}
__device__ __forceinline__ void mma_16816(float* c, const uint32_t* a, const uint32_t* b) {
    asm volatile("mma.sync.aligned.m16n8k16.row.col.f32.bf16.bf16.f32 "
                 "{%0,%1,%2,%3}, {%4,%5,%6,%7}, {%8,%9}, {%0,%1,%2,%3};"
                 : "+f"(c[0]), "+f"(c[1]), "+f"(c[2]), "+f"(c[3])
                 : "r"(a[0]), "r"(a[1]), "r"(a[2]), "r"(a[3]), "r"(b[0]), "r"(b[1]));
}

// ---------------- operand builders ----------------
// A-mode split of [vx|ax] concat: g_xcat3[b][blk*1024 + k], blocks [hi|lo|hi]
__global__ void concat_split_kernel(const float* __restrict__ vx, const float* __restrict__ ax) {
    int idx = blockIdx.x * blockDim.x + threadIdx.x;  // 1024*128
    int kv = idx & 127, b = idx >> 7;
    const float* src = (kv < 64) ? (vx + (size_t)b * 512 + kv * 8)
                                 : (ax + (size_t)b * 512 + (kv - 64) * 8);
    float4 x0 = *(const float4*)src, x1 = *(const float4*)(src + 4);
    float vals[8] = {x0.x, x0.y, x0.z, x0.w, x1.x, x1.y, x1.z, x1.w};
    Pack8 hi, lo;
    #pragma unroll
    for (int j = 0; j < 8; j++) split_hi_lo(vals[j], hi.s[j], lo.s[j]);
    size_t e0 = (size_t)b * 3072 + kv * 8;
    *(uint4*)(g_xcat3 + e0)        = hi.v;
    *(uint4*)(g_xcat3 + e0 + 1024) = lo.v;
    *(uint4*)(g_xcat3 + e0 + 2048) = hi.v;
}

// B-mode split: dst[r][3K], blocks [hi|hi|lo]
__global__ void split3B_kernel(const float* __restrict__ src, unsigned short* __restrict__ dst,
                               int Kv /* K/8 */, int K) {
    int idx = blockIdx.x * blockDim.x + threadIdx.x;  // R*Kv
    int kv = idx % Kv, r = idx / Kv;
    const float* s = src + (size_t)r * K + kv * 8;
    float4 x0 = *(const float4*)s, x1 = *(const float4*)(s + 4);
    float vals[8] = {x0.x, x0.y, x0.z, x0.w, x1.x, x1.y, x1.z, x1.w};
    Pack8 hi, lo;
    #pragma unroll
    for (int j = 0; j < 8; j++) split_hi_lo(vals[j], hi.s[j], lo.s[j]);
    size_t e0 = (size_t)r * 3 * K + kv * 8;
    *(uint4*)(dst + e0)         = hi.v;
    *(uint4*)(dst + e0 + K)     = hi.v;
    *(uint4*)(dst + e0 + 2 * K) = lo.v;
}

// conv2+mean collapse -> B-mode split directly: g_A23[c][blk*2048 + f*4+q]
__global__ void pre_A2_kernel(const float* __restrict__ w2) {
    int idx = blockIdx.x * blockDim.x + threadIdx.x;  // 512*512*4
    int q = idx & 3;
    int cf = idx >> 2;
    int f = cf & 511;
    int c = cf >> 9;
    int ip = q >> 1, jp = q & 1;
    const float* wb = w2 + (size_t)(c * 512 + f) * 9;
    float s = 0.f;
    #pragma unroll
    for (int i = 0; i < 2; i++)
        #pragma unroll
        for (int j = 0; j < 2; j++)
            s += wb[(ip - i + 1) * 3 + (jp - j + 1)];
    unsigned short hi, lo;
    split_hi_lo(0.25f * s, hi, lo);
    size_t e0 = (size_t)c * 6144 + f * 4 + q;
    g_A23[e0]        = hi;
    g_A23[e0 + 2048] = hi;
    g_A23[e0 + 4096] = lo;
}

// conv A operand: X3[r=(b,i)][blk*1536 + di*512 + f], blocks [hi|lo|hi], from vaT
__global__ void build_x3_kernel() {
    int idx = blockIdx.x * blockDim.x + threadIdx.x;   // 8192*3*64
    int fg = idx & 63;
    int di = (idx >> 6) % 3;
    int r  = idx / 192;
    int b = r >> 3, i = r & 7;
    int src = i + di - 1;
    float vals[8];
    if (src >= 0 && src < 8) {
        const float4* p = (const float4*)(g_vaT + ((size_t)(b * 8 + src) * 512) + fg * 8);
        float4 x0 = p[0], x1 = p[1];
        vals[0] = x0.x; vals[1] = x0.y; vals[2] = x0.z; vals[3] = x0.w;
        vals[4] = x1.x; vals[5] = x1.y; vals[6] = x1.z; vals[7] = x1.w;
    } else {
        #pragma unroll
        for (int j = 0; j < 8; j++) vals[j] = 0.f;
    }
    Pack8 hi, lo;
    #pragma unroll
    for (int j = 0; j < 8; j++) split_hi_lo(vals[j], hi.s[j], lo.s[j]);
    size_t e0 = (size_t)r * 4608 + di * 512 + fg * 8;
    *(uint4*)(g_X3 + e0)        = hi.v;
    *(uint4*)(g_X3 + e0 + 1536) = lo.v;
    *(uint4*)(g_X3 + e0 + 3072) = hi.v;
}

// conv B operand: W3[n=t*512+c][blk*1536 + di*512 + f], blocks [hi|hi|lo]
__global__ void build_w3_kernel(const float* __restrict__ c1w) {
    int idx = blockIdx.x * blockDim.x + threadIdx.x;   // 1536*3*64
    int fg = idx & 63;
    int di = (idx >> 6) % 3;
    int n  = idx / 192;
    int t = n >> 9, c = n & 511;
    Pack8 hi, lo;
    #pragma unroll
    for (int j = 0; j < 8; j++) {
        int f = fg * 8 + j;
        size_t base = ((size_t)(c * 512 + f) * 3 + di) * 3;
        float w;
        if (t == 0)      w = c1w[base] + c1w[base + 1] + c1w[base + 2];
        else if (t == 1) w = c1w[base];
        else             w = c1w[base + 2];
        split_hi_lo(w, hi.s[j], lo.s[j]);
    }
    size_t e0 = (size_t)n * 4608 + di * 512 + fg * 8;
    *(uint4*)(g_W3 + e0)        = hi.v;
    *(uint4*)(g_W3 + e0 + 1536) = hi.v;
    *(uint4*)(g_W3 + e0 + 3072) = lo.v;
}

// ---------------- unified HMMA GEMM ----------------
// C = A[M][Ks] * B[N=128/grid][Ks]^T, row-major K-contiguous, bf16.
// TM in {128,256}; N tile always 128. BK=32, double-buffered.
// MODE 0: outF[r*ldc+c] = acc                        (conv -> Y)
// MODE 1: outF[r*ldc+c] = relu(acc + bias[c])        (GEMM3 -> out)
// MODE 2: h3 split store: relu(acc + bias[c]) -> [z][r][3*512]   (GEMM1)
// MODE 3: vaT[(r*8+z)*512+g] = vx[r*512+g]*relu(acc+bias[g])     (GEMM2)
template <int TM, int MODE>
__global__ void __launch_bounds__((TM == 256) ? 512 : 256, (TM == 256) ? 1 : 2)
hmma_kernel(const unsigned short* __restrict__ A, const unsigned short* __restrict__ Bm,
            const float* __restrict__ bias, float* __restrict__ outF,
            unsigned short* __restrict__ outH, const float* __restrict__ vx,
            int Ks, int ldc, size_t batchA, size_t batchB, int batchBias)
{
    constexpr int THREADS = (TM == 256) ? 512 : 256;
    constexpr int ROWS = TM + 128;
    constexpr int CH = ROWS * 4 / THREADS;
    constexpr int WMC = TM / 64;
    constexpr int ABUF = TM * LDK;    // elements per A stage
    constexpr int BBUF = 128 * LDK;

    extern __shared__ __align__(16) unsigned short smem[];
    unsigned short* sA = smem;                 // [2][ABUF]
    unsigned short* sB = smem + 2 * ABUF;      // [2][BBUF]

    const int tid = threadIdx.x;
    const int wid = tid >> 5, lane = tid & 31;
    const int m0 = blockIdx.y * TM;
    const int n0 = blockIdx.x * 128;
    const int z  = blockIdx.z;
    const int wm = (wid % WMC) * 64;
    const int wn = (wid / WMC) * 32;

    A += (size_t)z * batchA;
    Bm += (size_t)z * batchB;
    if (MODE == 1 || MODE == 2 || MODE == 3) bias += (size_t)z * batchBias;

    // staging maps
    const unsigned short* gp[CH];
    unsigned short* sd[CH];
    int bstep[CH];
    #pragma unroll
    for (int t = 0; t < CH; t++) {
        int id = tid + t * THREADS;
        int r = id >> 2, q = id & 3;
        if (r < TM) {
            gp[t] = A + (size_t)(m0 + r) * Ks + q * 8;
            sd[t] = sA + r * LDK + q * 8;
            bstep[t] = ABUF;
        } else {
            gp[t] = Bm + (size_t)(n0 + r - TM) * Ks + q * 8;
            sd[t] = sB + (r - TM) * LDK + q * 8;
            bstep[t] = BBUF;
        }
    }

    float acc[4][4][4];
    #pragma unroll
    for (int i = 0; i < 4; i++)
        #pragma unroll
        for (int j = 0; j < 4; j++)
            #pragma unroll
            for (int q = 0; q < 4; q++) acc[i][j][q] = 0.f;

    const uint32_t sA_base = smem_u32(sA);
    const uint32_t sB_base = smem_u32(sB);
    const int aRow = wm + (lane & 15);
    const int aKof = (lane >> 4) * 8;
    const int bRow = wn + ((lane & 7) | ((lane >> 4) << 3));
    const int bKof = ((lane >> 3) & 1) * 8;

    uint4 rg[CH];
    #pragma unroll
    for (int t = 0; t < CH; t++) rg[t] = *(const uint4*)gp[t];
    #pragma unroll
    for (int t = 0; t < CH; t++) *(uint4*)sd[t] = rg[t];
    __syncthreads();

    const int NIT = Ks / 32;
    for (int it = 0; it < NIT; it++) {
        const int cur = it & 1;
        const bool more = (it + 1) < NIT;
        if (more) {
            #pragma unroll
            for (int t = 0; t < CH; t++)
                rg[t] = *(const uint4*)(gp[t] + (size_t)(it + 1) * 32);
        }
        const uint32_t aBuf = sA_base + cur * (ABUF * 2);
        const uint32_t bBuf = sB_base + cur * (BBUF * 2);
        #pragma unroll
        for (int ks = 0; ks < 32; ks += 16) {
            uint32_t af[4][4], bf[4][2];
            #pragma unroll
            for (int mt = 0; mt < 4; mt++)
                ldmatrix_x4(af[mt][0], af[mt][1], af[mt][2], af[mt][3],
                            aBuf + (uint32_t)(((aRow + mt * 16) * LDK + ks + aKof) * 2));
            #pragma unroll
            for (int np = 0; np < 2; np++)
                ldmatrix_x4(bf[np * 2][0], bf[np * 2][1], bf[np * 2 + 1][0], bf[np * 2 + 1][1],
                            bBuf + (uint32_t)(((bRow + np * 16) * LDK + ks + bKof) * 2));
            #pragma unroll
            for (int mt = 0; mt < 4; mt++)
                #pragma unroll
                for (int nt = 0; nt < 4; nt++)
                    mma_16816(acc[mt][nt], af[mt], bf[nt]);
        }
        if (more) {
            const int nxt = (it + 1) & 1;
            #pragma unroll
            for (int t = 0; t < CH; t++)
                *(uint4*)(sd[t] + nxt * bstep[t]) = rg[t];
        }
        __syncthreads();
    }

    // epilogue
    const int erow = lane >> 2;
    const int ecol = (lane & 3) * 2;
    #pragma unroll
    for (int mt = 0; mt < 4; mt++) {
        #pragma unroll
        for (int nt = 0; nt < 4; nt++) {
            const int r0 = m0 + wm + mt * 16 + erow;
            const int c  = n0 + wn + nt * 8 + ecol;
            const float* v = acc[mt][nt];
            if (MODE == 0) {
                *(float2*)&outF[(size_t)r0 * ldc + c] = make_float2(v[0], v[1]);
                *(float2*)&outF[(size_t)(r0 + 8) * ldc + c] = make_float2(v[2], v[3]);
            } else if (MODE == 1) {
                float b0 = bias[c], b1 = bias[c + 1];
                *(float2*)&outF[(size_t)r0 * ldc + c] =
                    make_float2(fmaxf(v[0] + b0, 0.f), fmaxf(v[1] + b1, 0.f));
                *(float2*)&outF[(size_t)(r0 + 8) * ldc + c] =
                    make_float2(fmaxf(v[2] + b0, 0.f), fmaxf(v[3] + b1, 0.f));
            } else if (MODE == 2) {
                float b0 = bias[c], b1 = bias[c + 1];
                int zz = c >> 9, f = c & 511;
                #pragma unroll
                for (int hr = 0; hr < 2; hr++) {
                    float y0 = fmaxf(v[hr * 2] + b0, 0.f);
                    float y1 = fmaxf(v[hr * 2 + 1] + b1, 0.f);
                    unsigned short h0, l0, h1, l1;
                    split_hi_lo(y0, h0, l0);
                    split_hi_lo(y1, h1, l1);
                    uint32_t hip = (uint32_t)h0 | ((uint32_t)h1 << 16);
                    uint32_t lop = (uint32_t)l0 | ((uint32_t)l1 << 16);
                    size_t base = ((size_t)zz * 1024 + (r0 + hr * 8)) * 1536 + f;
                    *(uint32_t*)&outH[base]        = hip;
                    *(uint32_t*)&outH[base + 512]  = lop;
                    *(uint32_t*)&outH[base + 1024] = hip;
                }
            } else {  // MODE 3
                float b0 = bias[c], b1 = bias[c + 1];
                #pragma unroll
                for (int hr = 0; hr < 2; hr++) {
                    int r = r0 + hr * 8;
                    float s0 = vx[(size_t)r * 512 + c];
                    float s1 = vx[(size_t)r * 512 + c + 1];
                    float y0 = s0 * fmaxf(v[hr * 2] + b0, 0.f);
                    float y1 = s1 * fmaxf(v[hr * 2 + 1] + b1, 0.f);
                    *(float2*)&outF[((size_t)r * 8 + z) * 512 + c] = make_float2(y0, y1);
                }
            }
        }
    }
}

// ---------------- pool: Y -> p3 (A-mode split) ----------------
__global__ void pool_split_kernel(const float* __restrict__ Y, const float* __restrict__ c1b) {
    int idx = blockIdx.x * blockDim.x + threadIdx.x;   // 1024*512
    int c = idx & 511, b = idx >> 9;
    float bias = c1b[c];
    float m00 = -1e30f, m01 = -1e30f, m10 = -1e30f, m11 = -1e30f;
    #pragma unroll
    for (int i = 0; i < 8; i++) {
        size_t base = (size_t)(b * 8 + i) * 1536;
        float yM = Y[base + c];
        float yB = Y[base + 512 + c];
        float yC = Y[base + 1024 + c];
        float vL = fmaxf(yM - yB, yM);
        float vR = fmaxf(yM - yC, yM);
        if (i < 4) { m00 = fmaxf(m00, vL); m01 = fmaxf(m01, vR); }
        else       { m10 = fmaxf(m10, vL); m11 = fmaxf(m11, vR); }
    }
    float p[4] = {m00 + bias, m01 + bias, m10 + bias, m11 + bias};
    ushort4 hi, lo;
    split_hi_lo(p[0], hi.x, lo.x);
    split_hi_lo(p[1], hi.y, lo.y);
    split_hi_lo(p[2], hi.z, lo.z);
    split_hi_lo(p[3], hi.w, lo.w);
    size_t e0 = (size_t)b * 6144 + c * 4;
    *(ushort4*)(g_p3 + e0)        = hi;
    *(ushort4*)(g_p3 + e0 + 2048) = lo;
    *(ushort4*)(g_p3 + e0 + 4096) = hi;
}

// ---------------- launch ----------------
extern "C" void kernel_launch(void* const* d_in, const int* in_sizes, int n_in,
                              void* d_out, int out_size) {
    (void)in_sizes; (void)n_in; (void)out_size;
    const float* vx  = (const float*)d_in[0];
    const float* ax  = (const float*)d_in[1];
    const float* W1  = (const float*)d_in[2];
    const float* b1  = (const float*)d_in[3];
    const float* W2  = (const float*)d_in[4];
    const float* b2  = (const float*)d_in[5];
    const float* c1w = (const float*)d_in[6];
    const float* c1b = (const float*)d_in[7];
    const float* c2w = (const float*)d_in[8];
    const float* c2b = (const float*)d_in[9];
    float* out = (float*)d_out;

    void *p_xcat3, *p_W13, *p_h3, *p_W23, *p_vaT, *p_X3, *p_W3, *p_Y, *p_p3, *p_A23;
    cudaGetSymbolAddress(&p_xcat3, g_xcat3);
    cudaGetSymbolAddress(&p_W13,   g_W13);
    cudaGetSymbolAddress(&p_h3,    g_h3);
    cudaGetSymbolAddress(&p_W23,   g_W23);
    cudaGetSymbolAddress(&p_vaT,   g_vaT);
    cudaGetSymbolAddress(&p_X3,    g_X3);
    cudaGetSymbolAddress(&p_W3,    g_W3);
    cudaGetSymbolAddress(&p_Y,     g_Y);
    cudaGetSymbolAddress(&p_p3,    g_p3);
    cudaGetSymbolAddress(&p_A23,   g_A23);

    const int SM256 = (2 * 256 + 2 * 128) * LDK * 2;  // 61440
    const int SM128 = (2 * 128 + 2 * 128) * LDK * 2;  // 40960
    cudaFuncSetAttribute(hmma_kernel<256, 0>, cudaFuncAttributeMaxDynamicSharedMemorySize, SM256);
    cudaFuncSetAttribute(hmma_kernel<256, 2>, cudaFuncAttributeMaxDynamicSharedMemorySize, SM256);
    cudaFuncSetAttribute(hmma_kernel<256, 3>, cudaFuncAttributeMaxDynamicSharedMemorySize, SM256);
    cudaFuncSetAttribute(hmma_kernel<128, 1>, cudaFuncAttributeMaxDynamicSharedMemorySize, SM128);

    // operand builders
    concat_split_kernel<<<512, 256>>>(vx, ax);                                   // xcat3
    split3B_kernel<<<2048, 256>>>(W1, (unsigned short*)p_W13, 128, 1024);        // W1_3
    split3B_kernel<<<1024, 256>>>(W2, (unsigned short*)p_W23, 64, 512);          // W2_3
    pre_A2_kernel<<<4096, 256>>>(c2w);                                           // A2_3
    build_w3_kernel<<<1152, 256>>>(c1w);                                         // W3

    // GEMM1: h3 = split(relu(xcat*W1^T + b1)); M=1024,N=4096,K=3072
    hmma_kernel<256, 2><<<dim3(32, 4), 512, SM256>>>(
        (const unsigned short*)p_xcat3, (const unsigned short*)p_W13, b1,
        nullptr, (unsigned short*)p_h3, nullptr, 3072, 0, 0, 0, 0);

    // GEMM2 (batch z): vaT = vx*relu(h_z*W2_z^T + b2_z); M=1024,N=512,K=1536
    hmma_kernel<256, 3><<<dim3(4, 4, 8), 512, SM256>>>(
        (const unsigned short*)p_h3, (const unsigned short*)p_W23, b2,
        (float*)p_vaT, nullptr, vx, 1536, 0,
        (size_t)1024 * 1536, (size_t)512 * 1536, 512);

    // conv A operand, then conv GEMM: Y = X3*W3^T; M=8192,N=1536,K=4608
    build_x3_kernel<<<6144, 256>>>();
    hmma_kernel<256, 0><<<dim3(12, 32), 512, SM256>>>(
        (const unsigned short*)p_X3, (const unsigned short*)p_W3, nullptr,
        (float*)p_Y, nullptr, nullptr, 4608, 1536, 0, 0, 0);

    // pool -> p3
    pool_split_kernel<<<2048, 256>>>((const float*)p_Y, c1b);

    // GEMM3: out = relu(p*A2^T + c2b); M=1024,N=512,K=6144
    hmma_kernel<128, 1><<<dim3(4, 8), 256, SM128>>>(
        (const unsigned short*)p_p3, (const unsigned short*)p_A23, c2b,
        out, nullptr, nullptr, 6144, 512, 0, 0, 0);
}